// round 6
// baseline (speedup 1.0000x reference)
#include <cuda_runtime.h>

#define NN 50000
#define EE 800000
#define GG 128
#define BN_EPS 1e-5f

// ---------------- scratch (static device allocations) ----------------
__device__ float g_deg[NN];          // degree, then dinv in place
__device__ float g_xe[NN * 128];     // encoder concat [me | we]
__device__ float g_x[NN * 64];       // encoder output x
__device__ float g_x1[NN * 64];      // layer-1 activated output
__device__ float g_h[NN * 64];       // per-layer transformed features
__device__ float g_o1[NN * 64];      // layer-1 aggregation accumulator
__device__ float g_o2[NN * 64];      // layer-2 aggregation accumulator
__device__ float g_bn1[128];         // sum|sumsq -> scale|shift
__device__ float g_bn2[128];
__device__ float g_xc[GG * 128];     // pooled [mean | max]
__device__ int   g_sh;               // 1 if indices are int64, 0 if int32

// constexpr-folded scratch buffer lookup
template<int ID> __device__ __forceinline__ float* gbuf() {
    if (ID == 0) return g_xe;
    if (ID == 1) return g_x;
    if (ID == 2) return g_x1;
    if (ID == 3) return g_h;
    if (ID == 4) return g_o1;
    if (ID == 5) return g_o2;
    return nullptr;
}
template<int ID> __device__ __forceinline__ float* gbn() {
    return (ID == 0) ? g_bn1 : g_bn2;
}

// clamped index fetch from a word-addressed (u32) view of the index buffer
__device__ __forceinline__ int eidx(const unsigned* __restrict__ w, long long elem, int sh) {
    int v = (int)w[elem << sh];
    v = v < 0 ? 0 : v;
    return v >= NN ? NN - 1 : v;
}

// ---------------- dtype detection ----------------
// If edge_index is int64 (values < 2^31, nonneg), the high 32-bit word of every
// element is 0. If it is int32, odd-position words are random node ids (odds of
// 128 consecutive random ids all being zero are nil).
__global__ void k_detect(const unsigned* __restrict__ eiw) {
    if (threadIdx.x == 0 && blockIdx.x == 0) {
        unsigned acc = 0;
        for (int i = 0; i < 128; i++) acc |= eiw[2 * i + 1];
        g_sh = (acc == 0) ? 1 : 0;
    }
}

// ---------------- init ----------------
__global__ void k_init() {
    int i = blockIdx.x * 256 + threadIdx.x;
    if (i < NN) g_deg[i] = 1.0f;                 // self loop contributes 1
    if (i < 128) { g_bn1[i] = 0.f; g_bn2[i] = 0.f; }
}

__global__ void k_degree(const unsigned* __restrict__ eiw) {
    int i = blockIdx.x * 256 + threadIdx.x;
    if (i >= EE) return;
    int sh = g_sh;
    atomicAdd(&g_deg[eidx(eiw, (long long)EE + i, sh)], 1.0f);
}

__global__ void k_rsqrt() {
    int i = blockIdx.x * 256 + threadIdx.x;
    if (i < NN) g_deg[i] = rsqrtf(g_deg[i]);
}

// ---------------- tiled GEMM: C[N,64] = act(A[N,K] @ W[K,64] + b) ----------------
// MODE 0: C = relu(acc + b)
// MODE 1: C = acc (raw h);  outb = b + dinv^2 * acc
// MODE 2: C = acc (raw h);  outb = b + xres + dinv^2 * acc
template<int K, int MODE, int SRC, int DST, int DSTOFF, int LDC, int OUTB, int RESB>
__global__ void __launch_bounds__(256) k_gemm(
        const float* __restrict__ Aext, const float* __restrict__ W,
        const float* __restrict__ bias)
{
    const float* A = (SRC < 0) ? Aext : gbuf<(SRC >= 0) ? SRC : 0>();
    float* C = gbuf<DST>() + DSTOFF;
    float* outb = gbuf<OUTB>();
    const float* xres = gbuf<RESB>();

    __shared__ float As[16][132];
    __shared__ float Ws[16][64];
    const int n0 = blockIdx.x * 128;
    const int tid = threadIdx.x;
    const int tcol = (tid & 15) * 4;      // 4 output cols
    const int trow = (tid >> 4) * 8;      // 8 nodes

    float4 acc[8];
#pragma unroll
    for (int i = 0; i < 8; i++) acc[i] = make_float4(0.f, 0.f, 0.f, 0.f);

    const float4* A4 = reinterpret_cast<const float4*>(A);
    const float4* W4 = reinterpret_cast<const float4*>(W);

#pragma unroll
    for (int kt = 0; kt < K / 16; kt++) {
        // stage A tile (128 nodes x 16 k), transposed
#pragma unroll
        for (int it = 0; it < 2; it++) {
            int f = tid + it * 256;
            int node = f >> 2, kc = f & 3;
            int gn = n0 + node;
            float4 a = make_float4(0.f, 0.f, 0.f, 0.f);
            if (gn < NN) a = A4[gn * (K / 4) + kt * 4 + kc];
            As[kc * 4 + 0][node] = a.x; As[kc * 4 + 1][node] = a.y;
            As[kc * 4 + 2][node] = a.z; As[kc * 4 + 3][node] = a.w;
        }
        // stage W tile (16 k x 64 cols)
        {
            int kk = tid >> 4, cw = tid & 15;
            *reinterpret_cast<float4*>(&Ws[kk][cw * 4]) = W4[(kt * 16 + kk) * 16 + cw];
        }
        __syncthreads();
#pragma unroll
        for (int kk = 0; kk < 16; kk++) {
            float4 w   = *reinterpret_cast<const float4*>(&Ws[kk][tcol]);
            float4 a03 = *reinterpret_cast<const float4*>(&As[kk][trow]);
            float4 a47 = *reinterpret_cast<const float4*>(&As[kk][trow + 4]);
            float av[8] = {a03.x, a03.y, a03.z, a03.w, a47.x, a47.y, a47.z, a47.w};
#pragma unroll
            for (int i = 0; i < 8; i++) {
                acc[i].x += av[i] * w.x; acc[i].y += av[i] * w.y;
                acc[i].z += av[i] * w.z; acc[i].w += av[i] * w.w;
            }
        }
        __syncthreads();
    }

    float4 b4 = *reinterpret_cast<const float4*>(&bias[tcol]);
#pragma unroll
    for (int i = 0; i < 8; i++) {
        int gn = n0 + trow + i;
        if (gn < NN) {
            float4 r = acc[i];
            if (MODE == 0) {
                r.x = fmaxf(r.x + b4.x, 0.f); r.y = fmaxf(r.y + b4.y, 0.f);
                r.z = fmaxf(r.z + b4.z, 0.f); r.w = fmaxf(r.w + b4.w, 0.f);
                *reinterpret_cast<float4*>(&C[gn * LDC + tcol]) = r;
            } else {
                *reinterpret_cast<float4*>(&C[gn * 64 + tcol]) = r;   // raw h
                float di = g_deg[gn];
                float s = di * di;
                float4 o;
                o.x = b4.x + s * r.x; o.y = b4.y + s * r.y;
                o.z = b4.z + s * r.z; o.w = b4.w + s * r.w;
                if (MODE == 2) {
                    float4 xr = *reinterpret_cast<const float4*>(&xres[gn * 64 + tcol]);
                    o.x += xr.x; o.y += xr.y; o.z += xr.z; o.w += xr.w;
                }
                *reinterpret_cast<float4*>(&outb[gn * 64 + tcol]) = o;
            }
        }
    }
}

// ---------------- edge scatter: out[col] += dinv[row]*dinv[col] * h[row] ----------------
template<int OUTB>
__global__ void __launch_bounds__(256) k_scatter(const unsigned* __restrict__ eiw)
{
    long long idx = (long long)blockIdx.x * 256 + threadIdx.x;
    int e = (int)(idx >> 4);   // 16 lanes per edge
    if (e >= EE) return;
    int sub = (int)(idx & 15);
    int sh = g_sh;
    int r = eidx(eiw, e, sh);
    int c = eidx(eiw, (long long)EE + e, sh);
    float nrm = g_deg[r] * g_deg[c];   // dinv values
    const float4* h4 = reinterpret_cast<const float4*>(g_h);
    float4 v = h4[r * 16 + sub];
    float* dst = gbuf<OUTB>() + c * 64 + sub * 4;
    atomicAdd(dst + 0, v.x * nrm);
    atomicAdd(dst + 1, v.y * nrm);
    atomicAdd(dst + 2, v.z * nrm);
    atomicAdd(dst + 3, v.w * nrm);
}

// ---------------- BN statistics ----------------
template<int SRCB, int BNB>
__global__ void k_bnstat()
{
    const float4* X = reinterpret_cast<const float4*>(gbuf<SRCB>());
    float* sums = gbn<BNB>();
    int t = blockIdx.x * blockDim.x + threadIdx.x;
    int stride = gridDim.x * blockDim.x;   // multiple of 16
    float4 s = make_float4(0.f, 0.f, 0.f, 0.f);
    float4 q = make_float4(0.f, 0.f, 0.f, 0.f);
    for (int i = t; i < NN * 16; i += stride) {
        float4 v = X[i];
        s.x += v.x; s.y += v.y; s.z += v.z; s.w += v.w;
        q.x += v.x * v.x; q.y += v.y * v.y; q.z += v.z * v.z; q.w += v.w * v.w;
    }
    s.x += __shfl_xor_sync(0xffffffffu, s.x, 16);
    s.y += __shfl_xor_sync(0xffffffffu, s.y, 16);
    s.z += __shfl_xor_sync(0xffffffffu, s.z, 16);
    s.w += __shfl_xor_sync(0xffffffffu, s.w, 16);
    q.x += __shfl_xor_sync(0xffffffffu, q.x, 16);
    q.y += __shfl_xor_sync(0xffffffffu, q.y, 16);
    q.z += __shfl_xor_sync(0xffffffffu, q.z, 16);
    q.w += __shfl_xor_sync(0xffffffffu, q.w, 16);
    if ((threadIdx.x & 16) == 0) {
        int c4 = (t & 15) * 4;
        atomicAdd(&sums[c4 + 0], s.x); atomicAdd(&sums[c4 + 1], s.y);
        atomicAdd(&sums[c4 + 2], s.z); atomicAdd(&sums[c4 + 3], s.w);
        atomicAdd(&sums[64 + c4 + 0], q.x); atomicAdd(&sums[64 + c4 + 1], q.y);
        atomicAdd(&sums[64 + c4 + 2], q.z); atomicAdd(&sums[64 + c4 + 3], q.w);
    }
}

template<int BNB>
__global__ void k_bnfin(const float* __restrict__ gamma, const float* __restrict__ beta)
{
    float* bn = gbn<BNB>();
    int c = threadIdx.x;   // 64 threads
    float s = bn[c], q = bn[64 + c];
    float mean = s * (1.0f / NN);
    float var = fmaxf(q * (1.0f / NN) - mean * mean, 0.f);
    float scale = gamma[c] * rsqrtf(var + BN_EPS);
    bn[c] = scale;
    bn[64 + c] = beta[c] - mean * scale;
}

// x1 = relu(bn1(o1))
__global__ void k_bnapply()
{
    const float4* X = reinterpret_cast<const float4*>(g_o1);
    float4* Y = reinterpret_cast<float4*>(g_x1);
    const float* bn = g_bn1;
    int i = blockIdx.x * 256 + threadIdx.x;
    if (i >= NN * 16) return;
    int c4 = (i & 15) * 4;
    float4 sc = *reinterpret_cast<const float4*>(&bn[c4]);
    float4 sh = *reinterpret_cast<const float4*>(&bn[64 + c4]);
    float4 v = X[i];
    v.x = fmaxf(v.x * sc.x + sh.x, 0.f);
    v.y = fmaxf(v.y * sc.y + sh.y, 0.f);
    v.z = fmaxf(v.z * sc.z + sh.z, 0.f);
    v.w = fmaxf(v.w * sc.w + sh.w, 0.f);
    Y[i] = v;
}

// ---------------- pooling (batch sorted -> binary search, no atomics) ----------------
__device__ __forceinline__ int lbound(const unsigned* __restrict__ bw, long long v, int sh) {
    int lo = 0, hi = NN;
    while (lo < hi) {
        int mid = (lo + hi) >> 1;
        long long bv = (long long)bw[(long long)mid << sh];
        if (bv < v) lo = mid + 1; else hi = mid;
    }
    return lo;
}

__global__ void __launch_bounds__(256) k_pool(const unsigned* __restrict__ bw)
{
    const float4* X = reinterpret_cast<const float4*>(g_o2);
    const float* bn = g_bn2;
    float* xc = g_xc;
    __shared__ float ssum[16][64];
    __shared__ float smax[16][64];
    int g = blockIdx.x;
    int sh0 = g_sh;
    int start = lbound(bw, (long long)g, sh0);
    int end   = lbound(bw, (long long)g + 1, sh0);
    int cc = threadIdx.x & 15;
    int chan = cc * 4;
    int rg = threadIdx.x >> 4;
    float4 sc = *reinterpret_cast<const float4*>(&bn[chan]);
    float4 sb = *reinterpret_cast<const float4*>(&bn[64 + chan]);
    float4 s = make_float4(0.f, 0.f, 0.f, 0.f);
    float4 m = make_float4(0.f, 0.f, 0.f, 0.f);
    for (int n = start + rg; n < end; n += 16) {
        float4 v = X[n * 16 + cc];
        v.x = fmaxf(v.x * sc.x + sb.x, 0.f);
        v.y = fmaxf(v.y * sc.y + sb.y, 0.f);
        v.z = fmaxf(v.z * sc.z + sb.z, 0.f);
        v.w = fmaxf(v.w * sc.w + sb.w, 0.f);
        s.x += v.x; s.y += v.y; s.z += v.z; s.w += v.w;
        m.x = fmaxf(m.x, v.x); m.y = fmaxf(m.y, v.y);
        m.z = fmaxf(m.z, v.z); m.w = fmaxf(m.w, v.w);
    }
    *reinterpret_cast<float4*>(&ssum[rg][chan]) = s;
    *reinterpret_cast<float4*>(&smax[rg][chan]) = m;
    __syncthreads();
    for (int off = 8; off >= 1; off >>= 1) {
        if (rg < off) {
            float4 a  = *reinterpret_cast<float4*>(&ssum[rg][chan]);
            float4 b  = *reinterpret_cast<float4*>(&ssum[rg + off][chan]);
            a.x += b.x; a.y += b.y; a.z += b.z; a.w += b.w;
            *reinterpret_cast<float4*>(&ssum[rg][chan]) = a;
            float4 am = *reinterpret_cast<float4*>(&smax[rg][chan]);
            float4 bm = *reinterpret_cast<float4*>(&smax[rg + off][chan]);
            am.x = fmaxf(am.x, bm.x); am.y = fmaxf(am.y, bm.y);
            am.z = fmaxf(am.z, bm.z); am.w = fmaxf(am.w, bm.w);
            *reinterpret_cast<float4*>(&smax[rg][chan]) = am;
        }
        __syncthreads();
    }
    if (rg == 0) {
        float inv = 1.0f / fmaxf((float)(end - start), 1.0f);
        float4 a = *reinterpret_cast<float4*>(&ssum[0][chan]);
        a.x *= inv; a.y *= inv; a.z *= inv; a.w *= inv;
        *reinterpret_cast<float4*>(&xc[g * 128 + chan]) = a;
        *reinterpret_cast<float4*>(&xc[g * 128 + 64 + chan]) =
            *reinterpret_cast<float4*>(&smax[0][chan]);
    }
}

// ---------------- heads: lat/lon MLPs, warp per (group, head) ----------------
__global__ void __launch_bounds__(256) k_heads(
        const float* __restrict__ Wa1, const float* __restrict__ ba1,
        const float* __restrict__ Wa2, const float* __restrict__ ba2,
        const float* __restrict__ Wo1, const float* __restrict__ bo1,
        const float* __restrict__ Wo2, const float* __restrict__ bo2,
        float* __restrict__ outp)
{
    const float* xc = g_xc;
    int gid = blockIdx.x * 8 + (threadIdx.x >> 5);   // 0..255
    if (gid >= 2 * GG) return;
    int lane = threadIdx.x & 31;
    int g = gid >> 1, head = gid & 1;
    const float* W1p = head ? Wo1 : Wa1;
    const float* b1p = head ? bo1 : ba1;
    const float* W2p = head ? Wo2 : Wa2;
    const float* b2p = head ? bo2 : ba2;
    float a0 = b1p[lane], a1 = b1p[lane + 32];
    const float* xg = xc + g * 128;
#pragma unroll 4
    for (int k = 0; k < 128; k++) {
        float v = xg[k];
        a0 += v * W1p[k * 64 + lane];
        a1 += v * W1p[k * 64 + lane + 32];
    }
    a0 = fmaxf(a0, 0.f); a1 = fmaxf(a1, 0.f);
    float o = a0 * W2p[lane] + a1 * W2p[lane + 32];
#pragma unroll
    for (int off = 16; off; off >>= 1) o += __shfl_xor_sync(0xffffffffu, o, off);
    if (lane == 0) outp[head * GG + g] = o + b2p[0];
}

// ---------------- launch ----------------
extern "C" void kernel_launch(void* const* d_in, const int* in_sizes, int n_in,
                              void* d_out, int out_size)
{
    const float*    metadata = (const float*)d_in[0];
    const float*    wf       = (const float*)d_in[1];
    const unsigned* eiw      = (const unsigned*)d_in[2];
    const unsigned* batchw   = (const unsigned*)d_in[3];
    const float* Wm  = (const float*)d_in[4];
    const float* bm  = (const float*)d_in[5];
    const float* Ww  = (const float*)d_in[6];
    const float* bw  = (const float*)d_in[7];
    const float* Wc  = (const float*)d_in[8];
    const float* bc  = (const float*)d_in[9];
    const float* W1  = (const float*)d_in[10];
    const float* b1  = (const float*)d_in[11];
    const float* W2  = (const float*)d_in[12];
    const float* b2  = (const float*)d_in[13];
    const float* g1  = (const float*)d_in[14];
    const float* be1 = (const float*)d_in[15];
    const float* g2  = (const float*)d_in[16];
    const float* be2 = (const float*)d_in[17];
    const float* Wla1 = (const float*)d_in[18];
    const float* bla1 = (const float*)d_in[19];
    const float* Wla2 = (const float*)d_in[20];
    const float* bla2 = (const float*)d_in[21];
    const float* Wlo1 = (const float*)d_in[22];
    const float* blo1 = (const float*)d_in[23];
    const float* Wlo2 = (const float*)d_in[24];
    const float* blo2 = (const float*)d_in[25];
    float* outp = (float*)d_out;

    const int NB = (NN + 255) / 256;
    const int GB = (NN + 127) / 128;                        // 391
    const int SB = (int)(((long long)EE * 16 + 255) / 256); // 50000

    k_detect<<<1, 32>>>(eiw);
    k_init<<<NB, 256>>>();
    k_degree<<<(EE + 255) / 256, 256>>>(eiw);
    k_rsqrt<<<NB, 256>>>();

    // encoders: me -> g_xe[:, :64], we -> g_xe[:, 64:], x = relu(xe @ Wc + bc)
    k_gemm<16,  0, -1, 0, 0,  128, 0, 0><<<GB, 256>>>(metadata, Wm, bm);
    k_gemm<128, 0, -1, 0, 64, 128, 0, 0><<<GB, 256>>>(wf, Ww, bw);
    k_gemm<128, 0,  0, 1, 0,  64,  0, 0><<<GB, 256>>>(nullptr, Wc, bc);

    // GCN layer 1: h = x@W1 (g_h), o1 seeded with b1 + dinv^2*h
    k_gemm<64, 1, 1, 3, 0, 64, 4, 0><<<GB, 256>>>(nullptr, W1, b1);
    k_scatter<4><<<SB, 256>>>(eiw);
    k_bnstat<4, 0><<<592, 256>>>();
    k_bnfin<0><<<1, 64>>>(g1, be1);
    k_bnapply<<<NN * 16 / 256, 256>>>();

    // GCN layer 2 (+ residual): h = x1@W2 (g_h), o2 seeded with b2 + x1 + dinv^2*h
    k_gemm<64, 2, 2, 3, 0, 64, 5, 2><<<GB, 256>>>(nullptr, W2, b2);
    k_scatter<5><<<SB, 256>>>(eiw);
    k_bnstat<5, 1><<<592, 256>>>();
    k_bnfin<1><<<1, 64>>>(g2, be2);

    // pooling + heads
    k_pool<<<GG, 256>>>(batchw);
    k_heads<<<32, 256>>>(Wla1, bla1, Wla2, bla2, Wlo1, blo1, Wlo2, blo2, outp);
}

// round 7
// speedup vs baseline: 1.2736x; 1.2736x over previous
#include <cuda_runtime.h>

#define NN 50000
#define EE 800000
#define GG 128
#define BN_EPS 1e-5f

// ---------------- scratch (static device allocations) ----------------
__device__ float g_deg[NN];          // dinv after k_rsqrt
__device__ int   g_cnt[NN];          // in-edge count (no self loop)
__device__ int   g_pos[NN];          // fill cursors
__device__ int   g_start[NN];        // CSR offsets (exclusive prefix of cnt)
__device__ int   g_csr[EE];          // CSR row lists per col
__device__ float g_xe[NN * 128];     // encoder concat [me | we]
__device__ float g_x[NN * 64];       // encoder output x
__device__ float g_h[NN * 64];       // hs = dinv[row] * (A@W) per layer
__device__ float g_o1[NN * 64];      // layer-1 aggregation accumulator
__device__ float g_o2[NN * 64];      // layer-2 aggregation accumulator
__device__ float g_bn1[128];         // sum|sumsq -> scale|shift
__device__ float g_bn2[128];
__device__ float g_xc[GG * 128];     // pooled [mean | max]
__device__ int   g_sh;               // 1 if indices are int64, 0 if int32

template<int ID> __device__ __forceinline__ float* gbuf() {
    if (ID == 0) return g_xe;
    if (ID == 1) return g_x;
    if (ID == 3) return g_h;
    if (ID == 4) return g_o1;
    if (ID == 5) return g_o2;
    return nullptr;
}
template<int ID> __device__ __forceinline__ float* gbn() {
    return (ID == 0) ? g_bn1 : g_bn2;
}

// clamped index fetch from a word-addressed (u32) view of the index buffer
__device__ __forceinline__ int eidx(const unsigned* __restrict__ w, long long elem, int sh) {
    int v = (int)w[elem << sh];
    v = v < 0 ? 0 : v;
    return v >= NN ? NN - 1 : v;
}

// ---------------- dtype detection (int64 vs int32 index buffers) ----------------
__global__ void k_detect(const unsigned* __restrict__ eiw) {
    if (threadIdx.x == 0 && blockIdx.x == 0) {
        unsigned acc = 0;
        for (int i = 0; i < 128; i++) acc |= eiw[2 * i + 1];
        g_sh = (acc == 0) ? 1 : 0;
    }
}

// ---------------- init / degree / CSR build ----------------
__global__ void k_init() {
    int i = blockIdx.x * 256 + threadIdx.x;
    if (i < NN) { g_cnt[i] = 0; g_pos[i] = 0; }
    if (i < 128) { g_bn1[i] = 0.f; g_bn2[i] = 0.f; }
}

__global__ void k_degree(const unsigned* __restrict__ eiw) {
    int i = blockIdx.x * 256 + threadIdx.x;
    if (i >= EE) return;
    atomicAdd(&g_cnt[eidx(eiw, (long long)EE + i, g_sh)], 1);
}

__global__ void k_rsqrt() {
    int i = blockIdx.x * 256 + threadIdx.x;
    if (i < NN) g_deg[i] = rsqrtf(1.0f + (float)g_cnt[i]);   // self loop adds 1
}

// single-block exclusive prefix scan of g_cnt -> g_start (1024 threads)
__global__ void __launch_bounds__(1024) k_scan() {
    __shared__ int ssum[1024];
    const int t = threadIdx.x;
    const int L = (NN + 1023) / 1024;   // 49
    int lo = t * L, hi = min(lo + L, NN);
    int s = 0;
    for (int i = lo; i < hi; i++) s += g_cnt[i];
    ssum[t] = s;
    __syncthreads();
    // inclusive scan over 1024 block sums
    for (int off = 1; off < 1024; off <<= 1) {
        int v = (t >= off) ? ssum[t - off] : 0;
        __syncthreads();
        ssum[t] += v;
        __syncthreads();
    }
    int run = (t == 0) ? 0 : ssum[t - 1];   // exclusive base for this chunk
    for (int i = lo; i < hi; i++) {
        g_start[i] = run;
        run += g_cnt[i];
    }
}

__global__ void k_fill(const unsigned* __restrict__ eiw) {
    int e = blockIdx.x * 256 + threadIdx.x;
    if (e >= EE) return;
    int sh = g_sh;
    int r = eidx(eiw, e, sh);
    int c = eidx(eiw, (long long)EE + e, sh);
    int p = g_start[c] + atomicAdd(&g_pos[c], 1);
    g_csr[p] = r;
}

// ---------------- tiled GEMM: C[N,64] = act(A[N,K] @ W[K,64] + b) ----------------
// MODE 0: C = relu(acc + b)
// MODE 1: hs = dinv*acc -> C;  outb = b + dinv*hs
// MODE 3: A = relu(bn1(o1)) on load; hs = dinv*acc -> C;
//         outb = b + dinv*hs + relu(bn1(o1 slice))   (residual recomputed)
template<int K, int MODE, int SRC, int DST, int DSTOFF, int LDC, int OUTB>
__global__ void __launch_bounds__(256) k_gemm(
        const float* __restrict__ Aext, const float* __restrict__ W,
        const float* __restrict__ bias)
{
    const float* A = (SRC < 0) ? Aext : gbuf<(SRC >= 0) ? SRC : 1>();
    float* C = gbuf<DST>() + DSTOFF;
    float* outb = gbuf<OUTB>();

    __shared__ float As[16][132];
    __shared__ float Ws[16][64];
    const int n0 = blockIdx.x * 128;
    const int tid = threadIdx.x;
    const int tcol = (tid & 15) * 4;      // 4 output cols
    const int trow = (tid >> 4) * 8;      // 8 nodes

    float4 acc[8];
#pragma unroll
    for (int i = 0; i < 8; i++) acc[i] = make_float4(0.f, 0.f, 0.f, 0.f);

    const float4* A4 = reinterpret_cast<const float4*>(A);
    const float4* W4 = reinterpret_cast<const float4*>(W);

#pragma unroll
    for (int kt = 0; kt < K / 16; kt++) {
        // stage A tile (128 nodes x 16 k), transposed
#pragma unroll
        for (int it = 0; it < 2; it++) {
            int f = tid + it * 256;
            int node = f >> 2, kc = f & 3;
            int gn = n0 + node;
            float4 a = make_float4(0.f, 0.f, 0.f, 0.f);
            if (gn < NN) a = A4[gn * (K / 4) + kt * 4 + kc];
            if (MODE == 3) {   // A = relu(bn1(o1)), channels = kt*16 + kc*4 ..
                int ch = kt * 16 + kc * 4;
                float4 sc = *reinterpret_cast<const float4*>(&g_bn1[ch]);
                float4 sv = *reinterpret_cast<const float4*>(&g_bn1[64 + ch]);
                a.x = fmaxf(a.x * sc.x + sv.x, 0.f);
                a.y = fmaxf(a.y * sc.y + sv.y, 0.f);
                a.z = fmaxf(a.z * sc.z + sv.z, 0.f);
                a.w = fmaxf(a.w * sc.w + sv.w, 0.f);
                if (gn >= NN) { a.x = a.y = a.z = a.w = 0.f; }
            }
            As[kc * 4 + 0][node] = a.x; As[kc * 4 + 1][node] = a.y;
            As[kc * 4 + 2][node] = a.z; As[kc * 4 + 3][node] = a.w;
        }
        {
            int kk = tid >> 4, cw = tid & 15;
            *reinterpret_cast<float4*>(&Ws[kk][cw * 4]) = W4[(kt * 16 + kk) * 16 + cw];
        }
        __syncthreads();
#pragma unroll
        for (int kk = 0; kk < 16; kk++) {
            float4 w   = *reinterpret_cast<const float4*>(&Ws[kk][tcol]);
            float4 a03 = *reinterpret_cast<const float4*>(&As[kk][trow]);
            float4 a47 = *reinterpret_cast<const float4*>(&As[kk][trow + 4]);
            float av[8] = {a03.x, a03.y, a03.z, a03.w, a47.x, a47.y, a47.z, a47.w};
#pragma unroll
            for (int i = 0; i < 8; i++) {
                acc[i].x += av[i] * w.x; acc[i].y += av[i] * w.y;
                acc[i].z += av[i] * w.z; acc[i].w += av[i] * w.w;
            }
        }
        __syncthreads();
    }

    float4 b4 = *reinterpret_cast<const float4*>(&bias[tcol]);
#pragma unroll
    for (int i = 0; i < 8; i++) {
        int gn = n0 + trow + i;
        if (gn < NN) {
            float4 r = acc[i];
            if (MODE == 0) {
                r.x = fmaxf(r.x + b4.x, 0.f); r.y = fmaxf(r.y + b4.y, 0.f);
                r.z = fmaxf(r.z + b4.z, 0.f); r.w = fmaxf(r.w + b4.w, 0.f);
                *reinterpret_cast<float4*>(&C[gn * LDC + tcol]) = r;
            } else {
                float di = g_deg[gn];
                float4 hs;
                hs.x = di * r.x; hs.y = di * r.y; hs.z = di * r.z; hs.w = di * r.w;
                *reinterpret_cast<float4*>(&C[gn * 64 + tcol]) = hs;
                float4 o;
                o.x = b4.x + di * hs.x; o.y = b4.y + di * hs.y;
                o.z = b4.z + di * hs.z; o.w = b4.w + di * hs.w;
                if (MODE == 3) {
                    float4 ov = *reinterpret_cast<const float4*>(&g_o1[gn * 64 + tcol]);
                    float4 sc = *reinterpret_cast<const float4*>(&g_bn1[tcol]);
                    float4 sv = *reinterpret_cast<const float4*>(&g_bn1[64 + tcol]);
                    o.x += fmaxf(ov.x * sc.x + sv.x, 0.f);
                    o.y += fmaxf(ov.y * sc.y + sv.y, 0.f);
                    o.z += fmaxf(ov.z * sc.z + sv.z, 0.f);
                    o.w += fmaxf(ov.w * sc.w + sv.w, 0.f);
                }
                *reinterpret_cast<float4*>(&outb[gn * 64 + tcol]) = o;
            }
        }
    }
}

// ---------------- CSR gather: out[c] += dinv[c] * sum_r hs[r]  (no atomics) ----------------
template<int OUTB>
__global__ void __launch_bounds__(256) k_gather()
{
    int idx = blockIdx.x * 256 + threadIdx.x;
    int node = idx >> 4;
    if (node >= NN) return;
    int sub = idx & 15;
    int j = g_start[node];
    int end = j + g_cnt[node];
    const float4* hs4 = reinterpret_cast<const float4*>(g_h);
    float4 acc = make_float4(0.f, 0.f, 0.f, 0.f);
    for (; j + 4 <= end; j += 4) {
        int r0 = g_csr[j], r1 = g_csr[j + 1], r2 = g_csr[j + 2], r3 = g_csr[j + 3];
        float4 v0 = hs4[r0 * 16 + sub];
        float4 v1 = hs4[r1 * 16 + sub];
        float4 v2 = hs4[r2 * 16 + sub];
        float4 v3 = hs4[r3 * 16 + sub];
        acc.x += (v0.x + v1.x) + (v2.x + v3.x);
        acc.y += (v0.y + v1.y) + (v2.y + v3.y);
        acc.z += (v0.z + v1.z) + (v2.z + v3.z);
        acc.w += (v0.w + v1.w) + (v2.w + v3.w);
    }
    for (; j < end; j++) {
        float4 v = hs4[g_csr[j] * 16 + sub];
        acc.x += v.x; acc.y += v.y; acc.z += v.z; acc.w += v.w;
    }
    float dc = g_deg[node];
    float4* out4 = reinterpret_cast<float4*>(gbuf<OUTB>());
    float4 o = out4[node * 16 + sub];
    o.x += dc * acc.x; o.y += dc * acc.y; o.z += dc * acc.z; o.w += dc * acc.w;
    out4[node * 16 + sub] = o;
}

// ---------------- BN statistics ----------------
template<int SRCB, int BNB>
__global__ void k_bnstat()
{
    const float4* X = reinterpret_cast<const float4*>(gbuf<SRCB>());
    float* sums = gbn<BNB>();
    int t = blockIdx.x * blockDim.x + threadIdx.x;
    int stride = gridDim.x * blockDim.x;
    float4 s = make_float4(0.f, 0.f, 0.f, 0.f);
    float4 q = make_float4(0.f, 0.f, 0.f, 0.f);
    for (int i = t; i < NN * 16; i += stride) {
        float4 v = X[i];
        s.x += v.x; s.y += v.y; s.z += v.z; s.w += v.w;
        q.x += v.x * v.x; q.y += v.y * v.y; q.z += v.z * v.z; q.w += v.w * v.w;
    }
    s.x += __shfl_xor_sync(0xffffffffu, s.x, 16);
    s.y += __shfl_xor_sync(0xffffffffu, s.y, 16);
    s.z += __shfl_xor_sync(0xffffffffu, s.z, 16);
    s.w += __shfl_xor_sync(0xffffffffu, s.w, 16);
    q.x += __shfl_xor_sync(0xffffffffu, q.x, 16);
    q.y += __shfl_xor_sync(0xffffffffu, q.y, 16);
    q.z += __shfl_xor_sync(0xffffffffu, q.z, 16);
    q.w += __shfl_xor_sync(0xffffffffu, q.w, 16);
    if ((threadIdx.x & 16) == 0) {
        int c4 = (t & 15) * 4;
        atomicAdd(&sums[c4 + 0], s.x); atomicAdd(&sums[c4 + 1], s.y);
        atomicAdd(&sums[c4 + 2], s.z); atomicAdd(&sums[c4 + 3], s.w);
        atomicAdd(&sums[64 + c4 + 0], q.x); atomicAdd(&sums[64 + c4 + 1], q.y);
        atomicAdd(&sums[64 + c4 + 2], q.z); atomicAdd(&sums[64 + c4 + 3], q.w);
    }
}

template<int BNB>
__global__ void k_bnfin(const float* __restrict__ gamma, const float* __restrict__ beta)
{
    float* bn = gbn<BNB>();
    int c = threadIdx.x;   // 64 threads
    float s = bn[c], q = bn[64 + c];
    float mean = s * (1.0f / NN);
    float var = fmaxf(q * (1.0f / NN) - mean * mean, 0.f);
    float scale = gamma[c] * rsqrtf(var + BN_EPS);
    bn[c] = scale;
    bn[64 + c] = beta[c] - mean * scale;
}

// ---------------- pooling (batch sorted -> binary search, no atomics) ----------------
__device__ __forceinline__ int lbound(const unsigned* __restrict__ bw, long long v, int sh) {
    int lo = 0, hi = NN;
    while (lo < hi) {
        int mid = (lo + hi) >> 1;
        long long bv = (long long)bw[(long long)mid << sh];
        if (bv < v) lo = mid + 1; else hi = mid;
    }
    return lo;
}

__global__ void __launch_bounds__(256) k_pool(const unsigned* __restrict__ bw)
{
    const float4* X = reinterpret_cast<const float4*>(g_o2);
    const float* bn = g_bn2;
    float* xc = g_xc;
    __shared__ float ssum[16][64];
    __shared__ float smax[16][64];
    int g = blockIdx.x;
    int sh0 = g_sh;
    int start = lbound(bw, (long long)g, sh0);
    int end   = lbound(bw, (long long)g + 1, sh0);
    int cc = threadIdx.x & 15;
    int chan = cc * 4;
    int rg = threadIdx.x >> 4;
    float4 sc = *reinterpret_cast<const float4*>(&bn[chan]);
    float4 sb = *reinterpret_cast<const float4*>(&bn[64 + chan]);
    float4 s = make_float4(0.f, 0.f, 0.f, 0.f);
    float4 m = make_float4(0.f, 0.f, 0.f, 0.f);
    for (int n = start + rg; n < end; n += 16) {
        float4 v = X[n * 16 + cc];
        v.x = fmaxf(v.x * sc.x + sb.x, 0.f);
        v.y = fmaxf(v.y * sc.y + sb.y, 0.f);
        v.z = fmaxf(v.z * sc.z + sb.z, 0.f);
        v.w = fmaxf(v.w * sc.w + sb.w, 0.f);
        s.x += v.x; s.y += v.y; s.z += v.z; s.w += v.w;
        m.x = fmaxf(m.x, v.x); m.y = fmaxf(m.y, v.y);
        m.z = fmaxf(m.z, v.z); m.w = fmaxf(m.w, v.w);
    }
    *reinterpret_cast<float4*>(&ssum[rg][chan]) = s;
    *reinterpret_cast<float4*>(&smax[rg][chan]) = m;
    __syncthreads();
    for (int off = 8; off >= 1; off >>= 1) {
        if (rg < off) {
            float4 a  = *reinterpret_cast<float4*>(&ssum[rg][chan]);
            float4 b  = *reinterpret_cast<float4*>(&ssum[rg + off][chan]);
            a.x += b.x; a.y += b.y; a.z += b.z; a.w += b.w;
            *reinterpret_cast<float4*>(&ssum[rg][chan]) = a;
            float4 am = *reinterpret_cast<float4*>(&smax[rg][chan]);
            float4 bm = *reinterpret_cast<float4*>(&smax[rg + off][chan]);
            am.x = fmaxf(am.x, bm.x); am.y = fmaxf(am.y, bm.y);
            am.z = fmaxf(am.z, bm.z); am.w = fmaxf(am.w, bm.w);
            *reinterpret_cast<float4*>(&smax[rg][chan]) = am;
        }
        __syncthreads();
    }
    if (rg == 0) {
        float inv = 1.0f / fmaxf((float)(end - start), 1.0f);
        float4 a = *reinterpret_cast<float4*>(&ssum[0][chan]);
        a.x *= inv; a.y *= inv; a.z *= inv; a.w *= inv;
        *reinterpret_cast<float4*>(&xc[g * 128 + chan]) = a;
        *reinterpret_cast<float4*>(&xc[g * 128 + 64 + chan]) =
            *reinterpret_cast<float4*>(&smax[0][chan]);
    }
}

// ---------------- heads: lat/lon MLPs, warp per (group, head) ----------------
__global__ void __launch_bounds__(256) k_heads(
        const float* __restrict__ Wa1, const float* __restrict__ ba1,
        const float* __restrict__ Wa2, const float* __restrict__ ba2,
        const float* __restrict__ Wo1, const float* __restrict__ bo1,
        const float* __restrict__ Wo2, const float* __restrict__ bo2,
        float* __restrict__ outp)
{
    const float* xc = g_xc;
    int gid = blockIdx.x * 8 + (threadIdx.x >> 5);   // 0..255
    if (gid >= 2 * GG) return;
    int lane = threadIdx.x & 31;
    int g = gid >> 1, head = gid & 1;
    const float* W1p = head ? Wo1 : Wa1;
    const float* b1p = head ? bo1 : ba1;
    const float* W2p = head ? Wo2 : Wa2;
    const float* b2p = head ? bo2 : ba2;
    float a0 = b1p[lane], a1 = b1p[lane + 32];
    const float* xg = xc + g * 128;
#pragma unroll 4
    for (int k = 0; k < 128; k++) {
        float v = xg[k];
        a0 += v * W1p[k * 64 + lane];
        a1 += v * W1p[k * 64 + lane + 32];
    }
    a0 = fmaxf(a0, 0.f); a1 = fmaxf(a1, 0.f);
    float o = a0 * W2p[lane] + a1 * W2p[lane + 32];
#pragma unroll
    for (int off = 16; off; off >>= 1) o += __shfl_xor_sync(0xffffffffu, o, off);
    if (lane == 0) outp[head * GG + g] = o + b2p[0];
}

// ---------------- launch ----------------
extern "C" void kernel_launch(void* const* d_in, const int* in_sizes, int n_in,
                              void* d_out, int out_size)
{
    const float*    metadata = (const float*)d_in[0];
    const float*    wf       = (const float*)d_in[1];
    const unsigned* eiw      = (const unsigned*)d_in[2];
    const unsigned* batchw   = (const unsigned*)d_in[3];
    const float* Wm  = (const float*)d_in[4];
    const float* bm  = (const float*)d_in[5];
    const float* Ww  = (const float*)d_in[6];
    const float* bw  = (const float*)d_in[7];
    const float* Wc  = (const float*)d_in[8];
    const float* bc  = (const float*)d_in[9];
    const float* W1  = (const float*)d_in[10];
    const float* b1  = (const float*)d_in[11];
    const float* W2  = (const float*)d_in[12];
    const float* b2  = (const float*)d_in[13];
    const float* g1  = (const float*)d_in[14];
    const float* be1 = (const float*)d_in[15];
    const float* g2  = (const float*)d_in[16];
    const float* be2 = (const float*)d_in[17];
    const float* Wla1 = (const float*)d_in[18];
    const float* bla1 = (const float*)d_in[19];
    const float* Wla2 = (const float*)d_in[20];
    const float* bla2 = (const float*)d_in[21];
    const float* Wlo1 = (const float*)d_in[22];
    const float* blo1 = (const float*)d_in[23];
    const float* Wlo2 = (const float*)d_in[24];
    const float* blo2 = (const float*)d_in[25];
    float* outp = (float*)d_out;

    const int NB = (NN + 255) / 256;
    const int EB = (EE + 255) / 256;
    const int GB = (NN + 127) / 128;             // 391
    const int AB = (NN * 16 + 255) / 256;        // 3125

    k_detect<<<1, 32>>>(eiw);
    k_init<<<NB, 256>>>();
    k_degree<<<EB, 256>>>(eiw);
    k_rsqrt<<<NB, 256>>>();
    k_scan<<<1, 1024>>>();
    k_fill<<<EB, 256>>>(eiw);

    // encoders: me -> g_xe[:, :64], we -> g_xe[:, 64:], x = relu(xe @ Wc + bc)
    k_gemm<16,  0, -1, 0, 0,  128, 0><<<GB, 256>>>(metadata, Wm, bm);
    k_gemm<128, 0, -1, 0, 64, 128, 0><<<GB, 256>>>(wf, Ww, bw);
    k_gemm<128, 0,  0, 1, 0,  64,  0><<<GB, 256>>>(nullptr, Wc, bc);

    // GCN layer 1: hs = dinv*(x@W1) -> g_h; o1 = b1 + dinv*hs; gather neighbors
    k_gemm<64, 1, 1, 3, 0, 64, 4><<<GB, 256>>>(nullptr, W1, b1);
    k_gather<4><<<AB, 256>>>();
    k_bnstat<4, 0><<<592, 256>>>();
    k_bnfin<0><<<1, 64>>>(g1, be1);

    // GCN layer 2: A = relu(bn1(o1)) fused; o2 = b2 + x1 + dinv*hs; gather
    k_gemm<64, 3, 4, 3, 0, 64, 5><<<GB, 256>>>(nullptr, W2, b2);
    k_gather<5><<<AB, 256>>>();
    k_bnstat<5, 1><<<592, 256>>>();
    k_bnfin<1><<<1, 64>>>(g2, be2);

    // pooling + heads
    k_pool<<<GG, 256>>>(batchw);
    k_heads<<<32, 256>>>(Wla1, bla1, Wla2, bla2, Wlo1, blo1, Wlo2, blo2, outp);
}

// round 8
// speedup vs baseline: 1.5580x; 1.2233x over previous
#include <cuda_runtime.h>

#define NN 50000
#define EE 800000
#define GG 128
#define BN_EPS 1e-5f

// ---------------- scratch ----------------
__device__ float g_deg[NN];          // dinv
__device__ int   g_cnt[NN];
__device__ int   g_pos[NN];
__device__ int   g_start[NN];
__device__ int   g_csr[EE];
__device__ float g_x[NN * 64];       // encoder output
__device__ float g_h[NN * 64];       // hs = dinv[row]*(A@W)
__device__ float g_o1[NN * 64];
__device__ float g_o2[NN * 64];
__device__ float g_bn1[128];         // raw sum|sumsq
__device__ float g_bn2[128];
__device__ int   g_sh;               // 1 if int64 indices, 0 if int32

template<int ID> __device__ __forceinline__ float* gbuf() {
    if (ID == 1) return g_x;
    if (ID == 3) return g_h;
    if (ID == 4) return g_o1;
    if (ID == 5) return g_o2;
    return nullptr;
}
template<int ID> __device__ __forceinline__ float* gbn() {
    return (ID == 0) ? g_bn1 : g_bn2;
}

__device__ __forceinline__ int eidx(const unsigned* __restrict__ w, long long elem, int sh) {
    int v = (int)w[elem << sh];
    v = v < 0 ? 0 : v;
    return v >= NN ? NN - 1 : v;
}

// ---------------- setup: zero buffers + dtype detect ----------------
__global__ void k_setup(const unsigned* __restrict__ eiw) {
    int i = blockIdx.x * 256 + threadIdx.x;
    if (i < NN) { g_cnt[i] = 0; g_pos[i] = 0; }
    if (i < 128) { g_bn1[i] = 0.f; g_bn2[i] = 0.f; }
    if (i == 0) {
        unsigned acc = 0;
        for (int k = 0; k < 128; k++) acc |= eiw[2 * k + 1];
        g_sh = (acc == 0) ? 1 : 0;
    }
}

__global__ void k_degree(const unsigned* __restrict__ eiw) {
    int i = blockIdx.x * 256 + threadIdx.x;
    if (i >= EE) return;
    atomicAdd(&g_cnt[eidx(eiw, (long long)EE + i, g_sh)], 1);
}

// single-block scan of g_cnt -> g_start, plus dinv = rsqrt(1+cnt)
__global__ void __launch_bounds__(1024) k_scanrsqrt() {
    __shared__ int ssum[1024];
    const int t = threadIdx.x;
    const int L = (NN + 1023) / 1024;
    int lo = t * L, hi = min(lo + L, NN);
    int s = 0;
    for (int i = lo; i < hi; i++) s += g_cnt[i];
    ssum[t] = s;
    __syncthreads();
    for (int off = 1; off < 1024; off <<= 1) {
        int v = (t >= off) ? ssum[t - off] : 0;
        __syncthreads();
        ssum[t] += v;
        __syncthreads();
    }
    int run = (t == 0) ? 0 : ssum[t - 1];
    for (int i = lo; i < hi; i++) {
        int c = g_cnt[i];
        g_start[i] = run;
        g_deg[i] = rsqrtf(1.0f + (float)c);
        run += c;
    }
}

__global__ void k_fill(const unsigned* __restrict__ eiw) {
    int e = blockIdx.x * 256 + threadIdx.x;
    if (e >= EE) return;
    int sh = g_sh;
    int r = eidx(eiw, e, sh);
    int c = eidx(eiw, (long long)EE + e, sh);
    int p = g_start[c] + atomicAdd(&g_pos[c], 1);
    g_csr[p] = r;
}

// ---------------- fused encoder: x = relu([relu(m@Wm+bm)|relu(wf@Ww+bw)]@Wc + bc) ----------------
__global__ void __launch_bounds__(256) k_encoder(
        const float* __restrict__ metadata, const float* __restrict__ wf,
        const float* __restrict__ Wm, const float* __restrict__ bm,
        const float* __restrict__ Ww, const float* __restrict__ bw,
        const float* __restrict__ Wc, const float* __restrict__ bc)
{
    __shared__ float As[16][132];
    __shared__ float Ws[16][64];
    __shared__ float As2[64][132];
    const int n0 = blockIdx.x * 128;
    const int tid = threadIdx.x;
    const int tcol = (tid & 15) * 4;
    const int trow = (tid >> 4) * 8;

    const float4* W4c = reinterpret_cast<const float4*>(Wc);
    float4 acc2[8];
#pragma unroll
    for (int i = 0; i < 8; i++) acc2[i] = make_float4(0.f, 0.f, 0.f, 0.f);

#pragma unroll
    for (int half = 0; half < 2; half++) {
        // ---- stage 1: me or we tile into acc ----
        const float* Ain = half ? wf : metadata;
        const float* W1  = half ? Ww : Wm;
        const float* B1  = half ? bw : bm;
        const int K = half ? 128 : 16;
        const float4* A4 = reinterpret_cast<const float4*>(Ain);
        const float4* W4 = reinterpret_cast<const float4*>(W1);

        float4 acc[8];
#pragma unroll
        for (int i = 0; i < 8; i++) acc[i] = make_float4(0.f, 0.f, 0.f, 0.f);

        for (int kt = 0; kt < K / 16; kt++) {
#pragma unroll
            for (int it = 0; it < 2; it++) {
                int f = tid + it * 256;
                int node = f >> 2, kc = f & 3;
                int gn = n0 + node;
                float4 a = make_float4(0.f, 0.f, 0.f, 0.f);
                if (gn < NN) a = A4[gn * (K / 4) + kt * 4 + kc];
                As[kc * 4 + 0][node] = a.x; As[kc * 4 + 1][node] = a.y;
                As[kc * 4 + 2][node] = a.z; As[kc * 4 + 3][node] = a.w;
            }
            {
                int kk = tid >> 4, cw = tid & 15;
                *reinterpret_cast<float4*>(&Ws[kk][cw * 4]) = W4[(kt * 16 + kk) * 16 + cw];
            }
            __syncthreads();
#pragma unroll
            for (int kk = 0; kk < 16; kk++) {
                float4 w   = *reinterpret_cast<const float4*>(&Ws[kk][tcol]);
                float4 a03 = *reinterpret_cast<const float4*>(&As[kk][trow]);
                float4 a47 = *reinterpret_cast<const float4*>(&As[kk][trow + 4]);
                float av[8] = {a03.x, a03.y, a03.z, a03.w, a47.x, a47.y, a47.z, a47.w};
#pragma unroll
                for (int i = 0; i < 8; i++) {
                    acc[i].x += av[i] * w.x; acc[i].y += av[i] * w.y;
                    acc[i].z += av[i] * w.z; acc[i].w += av[i] * w.w;
                }
            }
            __syncthreads();
        }

        // write relu(acc+b) transposed into As2 [channel][node]
        float4 b4 = *reinterpret_cast<const float4*>(&B1[tcol]);
#pragma unroll
        for (int i = 0; i < 8; i++) {
            int row = trow + i;
            As2[tcol + 0][row] = fmaxf(acc[i].x + b4.x, 0.f);
            As2[tcol + 1][row] = fmaxf(acc[i].y + b4.y, 0.f);
            As2[tcol + 2][row] = fmaxf(acc[i].z + b4.z, 0.f);
            As2[tcol + 3][row] = fmaxf(acc[i].w + b4.w, 0.f);
        }
        __syncthreads();

        // ---- stage 2 partial: acc2 += As2 @ Wc[half*64 .. +63] ----
        for (int kt = 0; kt < 4; kt++) {
            {
                int kk = tid >> 4, cw = tid & 15;
                *reinterpret_cast<float4*>(&Ws[kk][cw * 4]) =
                    W4c[(half * 64 + kt * 16 + kk) * 16 + cw];
            }
            __syncthreads();
#pragma unroll
            for (int kk = 0; kk < 16; kk++) {
                int k2 = kt * 16 + kk;
                float4 w   = *reinterpret_cast<const float4*>(&Ws[kk][tcol]);
                float4 a03 = *reinterpret_cast<const float4*>(&As2[k2][trow]);
                float4 a47 = *reinterpret_cast<const float4*>(&As2[k2][trow + 4]);
                float av[8] = {a03.x, a03.y, a03.z, a03.w, a47.x, a47.y, a47.z, a47.w};
#pragma unroll
                for (int i = 0; i < 8; i++) {
                    acc2[i].x += av[i] * w.x; acc2[i].y += av[i] * w.y;
                    acc2[i].z += av[i] * w.z; acc2[i].w += av[i] * w.w;
                }
            }
            __syncthreads();
        }
    }

    float4 bc4 = *reinterpret_cast<const float4*>(&bc[tcol]);
#pragma unroll
    for (int i = 0; i < 8; i++) {
        int gn = n0 + trow + i;
        if (gn < NN) {
            float4 r = acc2[i];
            r.x = fmaxf(r.x + bc4.x, 0.f); r.y = fmaxf(r.y + bc4.y, 0.f);
            r.z = fmaxf(r.z + bc4.z, 0.f); r.w = fmaxf(r.w + bc4.w, 0.f);
            *reinterpret_cast<float4*>(&g_x[gn * 64 + tcol]) = r;
        }
    }
}

// ---------------- GCN GEMM: hs = dinv*(A@W) -> g_h; seed outb ----------------
// MODE 1: A = g_x;            outb = b + dinv*hs
// MODE 3: A = relu(bn1(o1));  outb = b + dinv*hs + relu(bn1(o1))   (bnfin computed in-block)
template<int MODE, int SRCB, int OUTB>
__global__ void __launch_bounds__(256) k_gcn_gemm(
        const float* __restrict__ W, const float* __restrict__ bias,
        const float* __restrict__ gamma, const float* __restrict__ beta)
{
    const float* A = gbuf<SRCB>();
    float* outb = gbuf<OUTB>();

    __shared__ float As[16][132];
    __shared__ float Ws[16][64];
    __shared__ float sbn[128];
    const int n0 = blockIdx.x * 128;
    const int tid = threadIdx.x;
    const int tcol = (tid & 15) * 4;
    const int trow = (tid >> 4) * 8;

    if (MODE == 3 && tid < 64) {
        float s = g_bn1[tid], q = g_bn1[64 + tid];
        float mean = s * (1.0f / NN);
        float var = fmaxf(q * (1.0f / NN) - mean * mean, 0.f);
        float scale = gamma[tid] * rsqrtf(var + BN_EPS);
        sbn[tid] = scale;
        sbn[64 + tid] = beta[tid] - mean * scale;
    }
    if (MODE == 3) __syncthreads();

    float4 acc[8];
#pragma unroll
    for (int i = 0; i < 8; i++) acc[i] = make_float4(0.f, 0.f, 0.f, 0.f);

    const float4* A4 = reinterpret_cast<const float4*>(A);
    const float4* W4 = reinterpret_cast<const float4*>(W);

#pragma unroll
    for (int kt = 0; kt < 4; kt++) {
#pragma unroll
        for (int it = 0; it < 2; it++) {
            int f = tid + it * 256;
            int node = f >> 2, kc = f & 3;
            int gn = n0 + node;
            float4 a = make_float4(0.f, 0.f, 0.f, 0.f);
            if (gn < NN) a = A4[gn * 16 + kt * 4 + kc];
            if (MODE == 3) {
                int ch = kt * 16 + kc * 4;
                float4 sc = *reinterpret_cast<const float4*>(&sbn[ch]);
                float4 sv = *reinterpret_cast<const float4*>(&sbn[64 + ch]);
                a.x = fmaxf(a.x * sc.x + sv.x, 0.f);
                a.y = fmaxf(a.y * sc.y + sv.y, 0.f);
                a.z = fmaxf(a.z * sc.z + sv.z, 0.f);
                a.w = fmaxf(a.w * sc.w + sv.w, 0.f);
                if (gn >= NN) { a.x = a.y = a.z = a.w = 0.f; }
            }
            As[kc * 4 + 0][node] = a.x; As[kc * 4 + 1][node] = a.y;
            As[kc * 4 + 2][node] = a.z; As[kc * 4 + 3][node] = a.w;
        }
        {
            int kk = tid >> 4, cw = tid & 15;
            *reinterpret_cast<float4*>(&Ws[kk][cw * 4]) = W4[(kt * 16 + kk) * 16 + cw];
        }
        __syncthreads();
#pragma unroll
        for (int kk = 0; kk < 16; kk++) {
            float4 w   = *reinterpret_cast<const float4*>(&Ws[kk][tcol]);
            float4 a03 = *reinterpret_cast<const float4*>(&As[kk][trow]);
            float4 a47 = *reinterpret_cast<const float4*>(&As[kk][trow + 4]);
            float av[8] = {a03.x, a03.y, a03.z, a03.w, a47.x, a47.y, a47.z, a47.w};
#pragma unroll
            for (int i = 0; i < 8; i++) {
                acc[i].x += av[i] * w.x; acc[i].y += av[i] * w.y;
                acc[i].z += av[i] * w.z; acc[i].w += av[i] * w.w;
            }
        }
        __syncthreads();
    }

    float4 b4 = *reinterpret_cast<const float4*>(&bias[tcol]);
#pragma unroll
    for (int i = 0; i < 8; i++) {
        int gn = n0 + trow + i;
        if (gn < NN) {
            float di = g_deg[gn];
            float4 hs;
            hs.x = di * acc[i].x; hs.y = di * acc[i].y;
            hs.z = di * acc[i].z; hs.w = di * acc[i].w;
            *reinterpret_cast<float4*>(&g_h[gn * 64 + tcol]) = hs;
            float4 o;
            o.x = b4.x + di * hs.x; o.y = b4.y + di * hs.y;
            o.z = b4.z + di * hs.z; o.w = b4.w + di * hs.w;
            if (MODE == 3) {
                float4 ov = *reinterpret_cast<const float4*>(&g_o1[gn * 64 + tcol]);
                float4 sc = *reinterpret_cast<const float4*>(&sbn[tcol]);
                float4 sv = *reinterpret_cast<const float4*>(&sbn[64 + tcol]);
                o.x += fmaxf(ov.x * sc.x + sv.x, 0.f);
                o.y += fmaxf(ov.y * sc.y + sv.y, 0.f);
                o.z += fmaxf(ov.z * sc.z + sv.z, 0.f);
                o.w += fmaxf(ov.w * sc.w + sv.w, 0.f);
            }
            *reinterpret_cast<float4*>(&outb[gn * 64 + tcol]) = o;
        }
    }
}

// ---------------- gather + fused BN statistics ----------------
template<int OUTB, int BNB>
__global__ void __launch_bounds__(256) k_gatherbn()
{
    __shared__ float4 ss[256];
    __shared__ float4 sq[256];
    int tid = threadIdx.x;
    int idx = blockIdx.x * 256 + tid;
    int node = idx >> 4;
    int sub = idx & 15;
    float4 o = make_float4(0.f, 0.f, 0.f, 0.f);
    if (node < NN) {
        int j = g_start[node];
        int end = j + g_cnt[node];
        const float4* hs4 = reinterpret_cast<const float4*>(g_h);
        float4 acc = make_float4(0.f, 0.f, 0.f, 0.f);
        for (; j + 4 <= end; j += 4) {
            int r0 = g_csr[j], r1 = g_csr[j + 1], r2 = g_csr[j + 2], r3 = g_csr[j + 3];
            float4 v0 = hs4[r0 * 16 + sub];
            float4 v1 = hs4[r1 * 16 + sub];
            float4 v2 = hs4[r2 * 16 + sub];
            float4 v3 = hs4[r3 * 16 + sub];
            acc.x += (v0.x + v1.x) + (v2.x + v3.x);
            acc.y += (v0.y + v1.y) + (v2.y + v3.y);
            acc.z += (v0.z + v1.z) + (v2.z + v3.z);
            acc.w += (v0.w + v1.w) + (v2.w + v3.w);
        }
        for (; j < end; j++) {
            float4 v = hs4[g_csr[j] * 16 + sub];
            acc.x += v.x; acc.y += v.y; acc.z += v.z; acc.w += v.w;
        }
        float dc = g_deg[node];
        float4* out4 = reinterpret_cast<float4*>(gbuf<OUTB>());
        o = out4[node * 16 + sub];
        o.x += dc * acc.x; o.y += dc * acc.y; o.z += dc * acc.z; o.w += dc * acc.w;
        out4[node * 16 + sub] = o;
    }
    ss[tid] = o;
    sq[tid] = make_float4(o.x * o.x, o.y * o.y, o.z * o.z, o.w * o.w);
    __syncthreads();
#pragma unroll
    for (int off = 128; off >= 16; off >>= 1) {
        if (tid < off) {
            float4 a = ss[tid], b = ss[tid + off];
            a.x += b.x; a.y += b.y; a.z += b.z; a.w += b.w;
            ss[tid] = a;
            float4 c = sq[tid], d = sq[tid + off];
            c.x += d.x; c.y += d.y; c.z += d.z; c.w += d.w;
            sq[tid] = c;
        }
        __syncthreads();
    }
    if (tid < 16) {
        float* sums = gbn<BNB>();
        float4 a = ss[tid], c = sq[tid];
        atomicAdd(&sums[tid * 4 + 0], a.x); atomicAdd(&sums[tid * 4 + 1], a.y);
        atomicAdd(&sums[tid * 4 + 2], a.z); atomicAdd(&sums[tid * 4 + 3], a.w);
        atomicAdd(&sums[64 + tid * 4 + 0], c.x); atomicAdd(&sums[64 + tid * 4 + 1], c.y);
        atomicAdd(&sums[64 + tid * 4 + 2], c.z); atomicAdd(&sums[64 + tid * 4 + 3], c.w);
    }
}

// ---------------- pool + heads (bnfin2 computed in-block) ----------------
__device__ __forceinline__ int lbound(const unsigned* __restrict__ bw, long long v, int sh) {
    int lo = 0, hi = NN;
    while (lo < hi) {
        int mid = (lo + hi) >> 1;
        long long bv = (long long)bw[(long long)mid << sh];
        if (bv < v) lo = mid + 1; else hi = mid;
    }
    return lo;
}

__global__ void __launch_bounds__(256) k_poolheads(const unsigned* __restrict__ bw,
        const float* __restrict__ g2, const float* __restrict__ be2,
        const float* __restrict__ Wa1, const float* __restrict__ ba1,
        const float* __restrict__ Wa2, const float* __restrict__ ba2,
        const float* __restrict__ Wo1, const float* __restrict__ bo1,
        const float* __restrict__ Wo2, const float* __restrict__ bo2,
        float* __restrict__ outp)
{
    __shared__ float sbn[128];
    __shared__ float ssum[16][64];
    __shared__ float smax[16][64];
    __shared__ float sxc[128];
    const int tid = threadIdx.x;
    const int g = blockIdx.x;

    if (tid < 64) {
        float s = g_bn2[tid], q = g_bn2[64 + tid];
        float mean = s * (1.0f / NN);
        float var = fmaxf(q * (1.0f / NN) - mean * mean, 0.f);
        float scale = g2[tid] * rsqrtf(var + BN_EPS);
        sbn[tid] = scale;
        sbn[64 + tid] = be2[tid] - mean * scale;
    }
    __syncthreads();

    const float4* X = reinterpret_cast<const float4*>(g_o2);
    int sh0 = g_sh;
    int start = lbound(bw, (long long)g, sh0);
    int end   = lbound(bw, (long long)g + 1, sh0);
    int cc = tid & 15;
    int chan = cc * 4;
    int rg = tid >> 4;
    float4 sc = *reinterpret_cast<const float4*>(&sbn[chan]);
    float4 sv = *reinterpret_cast<const float4*>(&sbn[64 + chan]);
    float4 s = make_float4(0.f, 0.f, 0.f, 0.f);
    float4 m = make_float4(0.f, 0.f, 0.f, 0.f);
    for (int n = start + rg; n < end; n += 16) {
        float4 v = X[n * 16 + cc];
        v.x = fmaxf(v.x * sc.x + sv.x, 0.f);
        v.y = fmaxf(v.y * sc.y + sv.y, 0.f);
        v.z = fmaxf(v.z * sc.z + sv.z, 0.f);
        v.w = fmaxf(v.w * sc.w + sv.w, 0.f);
        s.x += v.x; s.y += v.y; s.z += v.z; s.w += v.w;
        m.x = fmaxf(m.x, v.x); m.y = fmaxf(m.y, v.y);
        m.z = fmaxf(m.z, v.z); m.w = fmaxf(m.w, v.w);
    }
    *reinterpret_cast<float4*>(&ssum[rg][chan]) = s;
    *reinterpret_cast<float4*>(&smax[rg][chan]) = m;
    __syncthreads();
    for (int off = 8; off >= 1; off >>= 1) {
        if (rg < off) {
            float4 a  = *reinterpret_cast<float4*>(&ssum[rg][chan]);
            float4 b  = *reinterpret_cast<float4*>(&ssum[rg + off][chan]);
            a.x += b.x; a.y += b.y; a.z += b.z; a.w += b.w;
            *reinterpret_cast<float4*>(&ssum[rg][chan]) = a;
            float4 am = *reinterpret_cast<float4*>(&smax[rg][chan]);
            float4 bm = *reinterpret_cast<float4*>(&smax[rg + off][chan]);
            am.x = fmaxf(am.x, bm.x); am.y = fmaxf(am.y, bm.y);
            am.z = fmaxf(am.z, bm.z); am.w = fmaxf(am.w, bm.w);
            *reinterpret_cast<float4*>(&smax[rg][chan]) = am;
        }
        __syncthreads();
    }
    if (rg == 0) {
        float inv = 1.0f / fmaxf((float)(end - start), 1.0f);
        float4 a = *reinterpret_cast<float4*>(&ssum[0][chan]);
        sxc[chan + 0] = a.x * inv; sxc[chan + 1] = a.y * inv;
        sxc[chan + 2] = a.z * inv; sxc[chan + 3] = a.w * inv;
        float4 mm = *reinterpret_cast<float4*>(&smax[0][chan]);
        sxc[64 + chan + 0] = mm.x; sxc[64 + chan + 1] = mm.y;
        sxc[64 + chan + 2] = mm.z; sxc[64 + chan + 3] = mm.w;
    }
    __syncthreads();

    int wid = tid >> 5;
    if (wid < 2) {
        int lane = tid & 31;
        int head = wid;
        const float* W1p = head ? Wo1 : Wa1;
        const float* b1p = head ? bo1 : ba1;
        const float* W2p = head ? Wo2 : Wa2;
        const float* b2p = head ? bo2 : ba2;
        float a0 = b1p[lane], a1 = b1p[lane + 32];
#pragma unroll 4
        for (int k = 0; k < 128; k++) {
            float v = sxc[k];
            a0 += v * W1p[k * 64 + lane];
            a1 += v * W1p[k * 64 + lane + 32];
        }
        a0 = fmaxf(a0, 0.f); a1 = fmaxf(a1, 0.f);
        float o = a0 * W2p[lane] + a1 * W2p[lane + 32];
#pragma unroll
        for (int off = 16; off; off >>= 1) o += __shfl_xor_sync(0xffffffffu, o, off);
        if (lane == 0) outp[head * GG + g] = o + b2p[0];
    }
}

// ---------------- launch ----------------
extern "C" void kernel_launch(void* const* d_in, const int* in_sizes, int n_in,
                              void* d_out, int out_size)
{
    const float*    metadata = (const float*)d_in[0];
    const float*    wf       = (const float*)d_in[1];
    const unsigned* eiw      = (const unsigned*)d_in[2];
    const unsigned* batchw   = (const unsigned*)d_in[3];
    const float* Wm  = (const float*)d_in[4];
    const float* bm  = (const float*)d_in[5];
    const float* Ww  = (const float*)d_in[6];
    const float* bw  = (const float*)d_in[7];
    const float* Wc  = (const float*)d_in[8];
    const float* bc  = (const float*)d_in[9];
    const float* W1  = (const float*)d_in[10];
    const float* b1  = (const float*)d_in[11];
    const float* W2  = (const float*)d_in[12];
    const float* b2  = (const float*)d_in[13];
    const float* g1  = (const float*)d_in[14];
    const float* be1 = (const float*)d_in[15];
    const float* g2  = (const float*)d_in[16];
    const float* be2 = (const float*)d_in[17];
    const float* Wla1 = (const float*)d_in[18];
    const float* bla1 = (const float*)d_in[19];
    const float* Wla2 = (const float*)d_in[20];
    const float* bla2 = (const float*)d_in[21];
    const float* Wlo1 = (const float*)d_in[22];
    const float* blo1 = (const float*)d_in[23];
    const float* Wlo2 = (const float*)d_in[24];
    const float* blo2 = (const float*)d_in[25];
    float* outp = (float*)d_out;

    const int NB = (NN + 255) / 256;
    const int EB = (EE + 255) / 256;
    const int GB = (NN + 127) / 128;          // 391
    const int AB = (NN * 16 + 255) / 256;     // 3125

    k_setup<<<NB, 256>>>(eiw);
    k_degree<<<EB, 256>>>(eiw);
    k_scanrsqrt<<<1, 1024>>>();
    k_fill<<<EB, 256>>>(eiw);

    k_encoder<<<GB, 256>>>(metadata, wf, Wm, bm, Ww, bw, Wc, bc);

    k_gcn_gemm<1, 1, 4><<<GB, 256>>>(W1, b1, nullptr, nullptr);
    k_gatherbn<4, 0><<<AB, 256>>>();

    k_gcn_gemm<3, 4, 5><<<GB, 256>>>(W2, b2, g1, be1);
    k_gatherbn<5, 1><<<AB, 256>>>();

    k_poolheads<<<GG, 256>>>(batchw, g2, be2,
                             Wla1, bla1, Wla2, bla2, Wlo1, blo1, Wlo2, blo2, outp);
}

// round 10
// speedup vs baseline: 1.6219x; 1.0411x over previous
#include <cuda_runtime.h>

#define NN 50000
#define EE 800000
#define GG 128
#define BN_EPS 1e-5f

// ---------------- scratch ----------------
__device__ float g_deg[NN];
__device__ int   g_cnt[NN];
__device__ int   g_pos[NN];
__device__ int   g_start[NN];
__device__ int   g_csr[EE];
__device__ float g_xe[NN * 128];
__device__ float g_x[NN * 64];
__device__ float g_h[NN * 64];
__device__ float g_o1[NN * 64];
__device__ float g_o2[NN * 64];
__device__ float g_bn1[128];
__device__ float g_bn2[128];
__device__ int   g_sh;

template<int ID> __device__ __forceinline__ float* gbuf() {
    if (ID == 0) return g_xe;
    if (ID == 1) return g_x;
    if (ID == 3) return g_h;
    if (ID == 4) return g_o1;
    if (ID == 5) return g_o2;
    return nullptr;
}
template<int ID> __device__ __forceinline__ float* gbn() {
    return (ID == 0) ? g_bn1 : g_bn2;
}

__device__ __forceinline__ int eidx(const unsigned* __restrict__ w, long long elem, int sh) {
    int v = (int)w[elem << sh];
    v = v < 0 ? 0 : v;
    return v >= NN ? NN - 1 : v;
}

__device__ __forceinline__ unsigned f2tf(float f) {
    unsigned u; asm("cvt.rna.tf32.f32 %0, %1;" : "=r"(u) : "f"(f)); return u;
}

__device__ __forceinline__ void mma_tf32(float* c, unsigned a0, unsigned a1,
                                         unsigned a2, unsigned a3,
                                         unsigned b0, unsigned b1) {
    asm volatile(
        "mma.sync.aligned.m16n8k8.row.col.f32.tf32.tf32.f32 "
        "{%0,%1,%2,%3}, {%4,%5,%6,%7}, {%8,%9}, {%0,%1,%2,%3};\n"
        : "+f"(c[0]), "+f"(c[1]), "+f"(c[2]), "+f"(c[3])
        : "r"(a0), "r"(a1), "r"(a2), "r"(a3), "r"(b0), "r"(b1));
}

// ---------------- setup / graph build ----------------
__global__ void k_setup(const unsigned* __restrict__ eiw) {
    int i = blockIdx.x * 256 + threadIdx.x;
    if (i < NN) { g_cnt[i] = 0; g_pos[i] = 0; }
    if (i < 128) { g_bn1[i] = 0.f; g_bn2[i] = 0.f; }
    if (i == 0) {
        unsigned acc = 0;
        for (int k = 0; k < 128; k++) acc |= eiw[2 * k + 1];
        g_sh = (acc == 0) ? 1 : 0;
    }
}

__global__ void k_degree(const unsigned* __restrict__ eiw) {
    int i = blockIdx.x * 256 + threadIdx.x;
    if (i >= EE) return;
    atomicAdd(&g_cnt[eidx(eiw, (long long)EE + i, g_sh)], 1);
}

__global__ void __launch_bounds__(1024) k_scanrsqrt() {
    __shared__ int ssum[1024];
    const int t = threadIdx.x;
    const int L = (NN + 1023) / 1024;
    int lo = t * L, hi = min(lo + L, NN);
    int s = 0;
    for (int i = lo; i < hi; i++) s += g_cnt[i];
    ssum[t] = s;
    __syncthreads();
    for (int off = 1; off < 1024; off <<= 1) {
        int v = (t >= off) ? ssum[t - off] : 0;
        __syncthreads();
        ssum[t] += v;
        __syncthreads();
    }
    int run = (t == 0) ? 0 : ssum[t - 1];
    for (int i = lo; i < hi; i++) {
        int c = g_cnt[i];
        g_start[i] = run;
        g_deg[i] = rsqrtf(1.0f + (float)c);
        run += c;
    }
}

__global__ void k_fill(const unsigned* __restrict__ eiw) {
    int e = blockIdx.x * 256 + threadIdx.x;
    if (e >= EE) return;
    int sh = g_sh;
    int r = eidx(eiw, e, sh);
    int c = eidx(eiw, (long long)EE + e, sh);
    int p = g_start[c] + atomicAdd(&g_pos[c], 1);
    g_csr[p] = r;
}

// ---------------- tf32 tensor-core GEMM: C[N,64] = act(A[N,K] @ W[K,64] + b) ----------------
// MODE 0: C = relu(acc+b) at stride LDC, offset DSTOFF into buf DSTB
// MODE 1: hs = dinv*acc -> g_h; outb = b + dinv*hs
// MODE 3: A = relu(bn1(o1)) on load; hs = dinv*acc -> g_h;
//         outb = b + dinv*hs + relu(bn1(o1))
template<int K, int MODE, int SRCB, int DSTB, int DSTOFF, int LDC, int OUTB>
__global__ void __launch_bounds__(256) k_gemm_tf32(
        const float* __restrict__ Aext, const float* __restrict__ W,
        const float* __restrict__ bias,
        const float* __restrict__ gamma, const float* __restrict__ beta)
{
    constexpr int KT = (K >= 32) ? 32 : 16;
    constexpr int NKT = K / KT;

    __shared__ unsigned Asm[128][KT + 4];
    __shared__ unsigned Wsm[KT][68];
    __shared__ float sbn[128];

    const float* A = (SRCB < 0) ? Aext : gbuf<(SRCB >= 0) ? SRCB : 0>();
    float* C = gbuf<DSTB>() + DSTOFF;
    float* outb = gbuf<OUTB>();

    const int n0 = blockIdx.x * 128;
    const int tid = threadIdx.x;
    const int warp = tid >> 5, lane = tid & 31;
    const int l4 = lane >> 2, lm4 = lane & 3;
    const int rw = warp * 16;

    if (MODE == 3) {
        if (tid < 64) {
            float s = g_bn1[tid], q = g_bn1[64 + tid];
            float mean = s * (1.0f / NN);
            float var = fmaxf(q * (1.0f / NN) - mean * mean, 0.f);
            float scale = gamma[tid] * rsqrtf(var + BN_EPS);
            sbn[tid] = scale;
            sbn[64 + tid] = beta[tid] - mean * scale;
        }
        __syncthreads();
    }

    float acc[8][4];
#pragma unroll
    for (int j = 0; j < 8; j++)
#pragma unroll
        for (int i = 0; i < 4; i++) acc[j][i] = 0.f;

    const float4* A4 = reinterpret_cast<const float4*>(A);
    const float4* W4 = reinterpret_cast<const float4*>(W);

#pragma unroll
    for (int kt = 0; kt < NKT; kt++) {
        // stage A (convert to tf32 bits)
#pragma unroll
        for (int idx = tid; idx < 128 * (KT / 4); idx += 256) {
            int row = idx / (KT / 4);
            int c4 = idx % (KT / 4);
            int gn = n0 + row;
            float4 a = make_float4(0.f, 0.f, 0.f, 0.f);
            if (gn < NN) {
                a = A4[gn * (K / 4) + kt * (KT / 4) + c4];
                if (MODE == 3) {
                    int ch = kt * KT + c4 * 4;
                    float4 sc = *reinterpret_cast<const float4*>(&sbn[ch]);
                    float4 sv = *reinterpret_cast<const float4*>(&sbn[64 + ch]);
                    a.x = fmaxf(a.x * sc.x + sv.x, 0.f);
                    a.y = fmaxf(a.y * sc.y + sv.y, 0.f);
                    a.z = fmaxf(a.z * sc.z + sv.z, 0.f);
                    a.w = fmaxf(a.w * sc.w + sv.w, 0.f);
                }
            }
            uint4 t;
            t.x = f2tf(a.x); t.y = f2tf(a.y); t.z = f2tf(a.z); t.w = f2tf(a.w);
            *reinterpret_cast<uint4*>(&Asm[row][c4 * 4]) = t;
        }
        // stage W
#pragma unroll
        for (int idx = tid; idx < KT * 16; idx += 256) {
            int k = idx / 16, c4 = idx % 16;
            float4 w = W4[(kt * KT + k) * 16 + c4];
            uint4 t;
            t.x = f2tf(w.x); t.y = f2tf(w.y); t.z = f2tf(w.z); t.w = f2tf(w.w);
            *reinterpret_cast<uint4*>(&Wsm[k][c4 * 4]) = t;
        }
        __syncthreads();

#pragma unroll
        for (int ks = 0; ks < KT / 8; ks++) {
            int kb = ks * 8;
            unsigned a0 = Asm[rw + l4][kb + lm4];
            unsigned a1 = Asm[rw + l4 + 8][kb + lm4];
            unsigned a2 = Asm[rw + l4][kb + lm4 + 4];
            unsigned a3 = Asm[rw + l4 + 8][kb + lm4 + 4];
#pragma unroll
            for (int j = 0; j < 8; j++) {
                unsigned b0 = Wsm[kb + lm4][j * 8 + l4];
                unsigned b1 = Wsm[kb + 4 + lm4][j * 8 + l4];
                mma_tf32(acc[j], a0, a1, a2, a3, b0, b1);
            }
        }
        __syncthreads();
    }

    // epilogue: thread owns rows r0=rw+l4, r1=r0+8; cols 8j + 2*lm4 (+1)
    int r0 = n0 + rw + l4;
    int r1 = r0 + 8;
    if (MODE == 0) {
#pragma unroll
        for (int j = 0; j < 8; j++) {
            int cj = j * 8 + lm4 * 2;
            float b0v = bias[cj], b1v = bias[cj + 1];
            if (r0 < NN) {
                float2 v = make_float2(fmaxf(acc[j][0] + b0v, 0.f),
                                       fmaxf(acc[j][1] + b1v, 0.f));
                *reinterpret_cast<float2*>(&C[r0 * LDC + cj]) = v;
            }
            if (r1 < NN) {
                float2 v = make_float2(fmaxf(acc[j][2] + b0v, 0.f),
                                       fmaxf(acc[j][3] + b1v, 0.f));
                *reinterpret_cast<float2*>(&C[r1 * LDC + cj]) = v;
            }
        }
    } else {
        float di0 = (r0 < NN) ? g_deg[r0] : 0.f;
        float di1 = (r1 < NN) ? g_deg[r1] : 0.f;
#pragma unroll
        for (int j = 0; j < 8; j++) {
            int cj = j * 8 + lm4 * 2;
            float b0v = bias[cj], b1v = bias[cj + 1];
            if (r0 < NN) {
                float hx = di0 * acc[j][0], hy = di0 * acc[j][1];
                *reinterpret_cast<float2*>(&g_h[r0 * 64 + cj]) = make_float2(hx, hy);
                float ox = b0v + di0 * hx, oy = b1v + di0 * hy;
                if (MODE == 3) {
                    float2 ov = *reinterpret_cast<const float2*>(&g_o1[r0 * 64 + cj]);
                    ox += fmaxf(ov.x * sbn[cj] + sbn[64 + cj], 0.f);
                    oy += fmaxf(ov.y * sbn[cj + 1] + sbn[64 + cj + 1], 0.f);
                }
                *reinterpret_cast<float2*>(&outb[r0 * 64 + cj]) = make_float2(ox, oy);
            }
            if (r1 < NN) {
                float hx = di1 * acc[j][2], hy = di1 * acc[j][3];
                *reinterpret_cast<float2*>(&g_h[r1 * 64 + cj]) = make_float2(hx, hy);
                float ox = b0v + di1 * hx, oy = b1v + di1 * hy;
                if (MODE == 3) {
                    float2 ov = *reinterpret_cast<const float2*>(&g_o1[r1 * 64 + cj]);
                    ox += fmaxf(ov.x * sbn[cj] + sbn[64 + cj], 0.f);
                    oy += fmaxf(ov.y * sbn[cj + 1] + sbn[64 + cj + 1], 0.f);
                }
                *reinterpret_cast<float2*>(&outb[r1 * 64 + cj]) = make_float2(ox, oy);
            }
        }
    }
}

// ---------------- gather + fused BN statistics ----------------
template<int OUTB, int BNB>
__global__ void __launch_bounds__(256) k_gatherbn()
{
    __shared__ float4 ss[256];
    __shared__ float4 sq[256];
    int tid = threadIdx.x;
    int idx = blockIdx.x * 256 + tid;
    int node = idx >> 4;
    int sub = idx & 15;
    float4 o = make_float4(0.f, 0.f, 0.f, 0.f);
    if (node < NN) {
        int j = g_start[node];
        int end = j + g_cnt[node];
        const float4* hs4 = reinterpret_cast<const float4*>(g_h);
        float4 acc = make_float4(0.f, 0.f, 0.f, 0.f);
        for (; j + 4 <= end; j += 4) {
            int r0 = g_csr[j], r1 = g_csr[j + 1], r2 = g_csr[j + 2], r3 = g_csr[j + 3];
            float4 v0 = hs4[r0 * 16 + sub];
            float4 v1 = hs4[r1 * 16 + sub];
            float4 v2 = hs4[r2 * 16 + sub];
            float4 v3 = hs4[r3 * 16 + sub];
            acc.x += (v0.x + v1.x) + (v2.x + v3.x);
            acc.y += (v0.y + v1.y) + (v2.y + v3.y);
            acc.z += (v0.z + v1.z) + (v2.z + v3.z);
            acc.w += (v0.w + v1.w) + (v2.w + v3.w);
        }
        for (; j < end; j++) {
            float4 v = hs4[g_csr[j] * 16 + sub];
            acc.x += v.x; acc.y += v.y; acc.z += v.z; acc.w += v.w;
        }
        float dc = g_deg[node];
        float4* out4 = reinterpret_cast<float4*>(gbuf<OUTB>());
        o = out4[node * 16 + sub];
        o.x += dc * acc.x; o.y += dc * acc.y; o.z += dc * acc.z; o.w += dc * acc.w;
        out4[node * 16 + sub] = o;
    }
    ss[tid] = o;
    sq[tid] = make_float4(o.x * o.x, o.y * o.y, o.z * o.z, o.w * o.w);
    __syncthreads();
#pragma unroll
    for (int off = 128; off >= 16; off >>= 1) {
        if (tid < off) {
            float4 a = ss[tid], b = ss[tid + off];
            a.x += b.x; a.y += b.y; a.z += b.z; a.w += b.w;
            ss[tid] = a;
            float4 c = sq[tid], d = sq[tid + off];
            c.x += d.x; c.y += d.y; c.z += d.z; c.w += d.w;
            sq[tid] = c;
        }
        __syncthreads();
    }
    if (tid < 16) {
        float* sums = gbn<BNB>();
        float4 a = ss[tid], c = sq[tid];
        atomicAdd(&sums[tid * 4 + 0], a.x); atomicAdd(&sums[tid * 4 + 1], a.y);
        atomicAdd(&sums[tid * 4 + 2], a.z); atomicAdd(&sums[tid * 4 + 3], a.w);
        atomicAdd(&sums[64 + tid * 4 + 0], c.x); atomicAdd(&sums[64 + tid * 4 + 1], c.y);
        atomicAdd(&sums[64 + tid * 4 + 2], c.z); atomicAdd(&sums[64 + tid * 4 + 3], c.w);
    }
}

// ---------------- pool + heads ----------------
__device__ __forceinline__ int lbound(const unsigned* __restrict__ bw, long long v, int sh) {
    int lo = 0, hi = NN;
    while (lo < hi) {
        int mid = (lo + hi) >> 1;
        long long bv = (long long)bw[(long long)mid << sh];
        if (bv < v) lo = mid + 1; else hi = mid;
    }
    return lo;
}

__global__ void __launch_bounds__(256) k_poolheads(const unsigned* __restrict__ bw,
        const float* __restrict__ g2, const float* __restrict__ be2,
        const float* __restrict__ Wa1, const float* __restrict__ ba1,
        const float* __restrict__ Wa2, const float* __restrict__ ba2,
        const float* __restrict__ Wo1, const float* __restrict__ bo1,
        const float* __restrict__ Wo2, const float* __restrict__ bo2,
        float* __restrict__ outp)
{
    __shared__ float sbn[128];
    __shared__ float ssum[16][64];
    __shared__ float smax[16][64];
    __shared__ float sxc[128];
    const int tid = threadIdx.x;
    const int g = blockIdx.x;

    if (tid < 64) {
        float s = g_bn2[tid], q = g_bn2[64 + tid];
        float mean = s * (1.0f / NN);
        float var = fmaxf(q * (1.0f / NN) - mean * mean, 0.f);
        float scale = g2[tid] * rsqrtf(var + BN_EPS);
        sbn[tid] = scale;
        sbn[64 + tid] = be2[tid] - mean * scale;
    }
    __syncthreads();

    const float4* X = reinterpret_cast<const float4*>(g_o2);
    int sh0 = g_sh;
    int start = lbound(bw, (long long)g, sh0);
    int end   = lbound(bw, (long long)g + 1, sh0);
    int cc = tid & 15;
    int chan = cc * 4;
    int rg = tid >> 4;
    float4 sc = *reinterpret_cast<const float4*>(&sbn[chan]);
    float4 sv = *reinterpret_cast<const float4*>(&sbn[64 + chan]);
    float4 s = make_float4(0.f, 0.f, 0.f, 0.f);
    float4 m = make_float4(0.f, 0.f, 0.f, 0.f);
    for (int n = start + rg; n < end; n += 16) {
        float4 v = X[n * 16 + cc];
        v.x = fmaxf(v.x * sc.x + sv.x, 0.f);
        v.y = fmaxf(v.y * sc.y + sv.y, 0.f);
        v.z = fmaxf(v.z * sc.z + sv.z, 0.f);
        v.w = fmaxf(v.w * sc.w + sv.w, 0.f);
        s.x += v.x; s.y += v.y; s.z += v.z; s.w += v.w;
        m.x = fmaxf(m.x, v.x); m.y = fmaxf(m.y, v.y);
        m.z = fmaxf(m.z, v.z); m.w = fmaxf(m.w, v.w);
    }
    *reinterpret_cast<float4*>(&ssum[rg][chan]) = s;
    *reinterpret_cast<float4*>(&smax[rg][chan]) = m;
    __syncthreads();
    for (int off = 8; off >= 1; off >>= 1) {
        if (rg < off) {
            float4 a  = *reinterpret_cast<float4*>(&ssum[rg][chan]);
            float4 b  = *reinterpret_cast<float4*>(&ssum[rg + off][chan]);
            a.x += b.x; a.y += b.y; a.z += b.z; a.w += b.w;
            *reinterpret_cast<float4*>(&ssum[rg][chan]) = a;
            float4 am = *reinterpret_cast<float4*>(&smax[rg][chan]);
            float4 bm = *reinterpret_cast<float4*>(&smax[rg + off][chan]);
            am.x = fmaxf(am.x, bm.x); am.y = fmaxf(am.y, bm.y);
            am.z = fmaxf(am.z, bm.z); am.w = fmaxf(am.w, bm.w);
            *reinterpret_cast<float4*>(&smax[rg][chan]) = am;
        }
        __syncthreads();
    }
    if (rg == 0) {
        float inv = 1.0f / fmaxf((float)(end - start), 1.0f);
        float4 a = *reinterpret_cast<float4*>(&ssum[0][chan]);
        sxc[chan + 0] = a.x * inv; sxc[chan + 1] = a.y * inv;
        sxc[chan + 2] = a.z * inv; sxc[chan + 3] = a.w * inv;
        float4 mm = *reinterpret_cast<float4*>(&smax[0][chan]);
        sxc[64 + chan + 0] = mm.x; sxc[64 + chan + 1] = mm.y;
        sxc[64 + chan + 2] = mm.z; sxc[64 + chan + 3] = mm.w;
    }
    __syncthreads();

    int wid = tid >> 5;
    if (wid < 2) {
        int lane = tid & 31;
        int head = wid;
        const float* W1p = head ? Wo1 : Wa1;
        const float* b1p = head ? bo1 : ba1;
        const float* W2p = head ? Wo2 : Wa2;
        const float* b2p = head ? bo2 : ba2;
        float a0 = b1p[lane], a1 = b1p[lane + 32];
#pragma unroll 4
        for (int k = 0; k < 128; k++) {
            float v = sxc[k];
            a0 += v * W1p[k * 64 + lane];
            a1 += v * W1p[k * 64 + lane + 32];
        }
        a0 = fmaxf(a0, 0.f); a1 = fmaxf(a1, 0.f);
        float o = a0 * W2p[lane] + a1 * W2p[lane + 32];
#pragma unroll
        for (int off = 16; off; off >>= 1) o += __shfl_xor_sync(0xffffffffu, o, off);
        if (lane == 0) outp[head * GG + g] = o + b2p[0];
    }
}

// ---------------- launch ----------------
extern "C" void kernel_launch(void* const* d_in, const int* in_sizes, int n_in,
                              void* d_out, int out_size)
{
    const float*    metadata = (const float*)d_in[0];
    const float*    wf       = (const float*)d_in[1];
    const unsigned* eiw      = (const unsigned*)d_in[2];
    const unsigned* batchw   = (const unsigned*)d_in[3];
    const float* Wm  = (const float*)d_in[4];
    const float* bm  = (const float*)d_in[5];
    const float* Ww  = (const float*)d_in[6];
    const float* bw  = (const float*)d_in[7];
    const float* Wc  = (const float*)d_in[8];
    const float* bc  = (const float*)d_in[9];
    const float* W1  = (const float*)d_in[10];
    const float* b1  = (const float*)d_in[11];
    const float* W2  = (const float*)d_in[12];
    const float* b2  = (const float*)d_in[13];
    const float* g1  = (const float*)d_in[14];
    const float* be1 = (const float*)d_in[15];
    const float* g2  = (const float*)d_in[16];
    const float* be2 = (const float*)d_in[17];
    const float* Wla1 = (const float*)d_in[18];
    const float* bla1 = (const float*)d_in[19];
    const float* Wla2 = (const float*)d_in[20];
    const float* bla2 = (const float*)d_in[21];
    const float* Wlo1 = (const float*)d_in[22];
    const float* blo1 = (const float*)d_in[23];
    const float* Wlo2 = (const float*)d_in[24];
    const float* blo2 = (const float*)d_in[25];
    float* outp = (float*)d_out;

    const int NB = (NN + 255) / 256;
    const int EB = (EE + 255) / 256;
    const int GB = (NN + 127) / 128;          // 391
    const int AB = (NN * 16 + 255) / 256;     // 3125

    k_setup<<<NB, 256>>>(eiw);
    k_degree<<<EB, 256>>>(eiw);
    k_scanrsqrt<<<1, 1024>>>();
    k_fill<<<EB, 256>>>(eiw);

    // encoders (tf32): me -> xe[:, :64], we -> xe[:, 64:], x = relu(xe @ Wc + bc)
    k_gemm_tf32<16,  0, -1, 0, 0,  128, 0><<<GB, 256>>>(metadata, Wm, bm, nullptr, nullptr);
    k_gemm_tf32<128, 0, -1, 0, 64, 128, 0><<<GB, 256>>>(wf, Ww, bw, nullptr, nullptr);
    k_gemm_tf32<128, 0,  0, 1, 0,  64,  0><<<GB, 256>>>(nullptr, Wc, bc, nullptr, nullptr);

    // GCN layer 1
    k_gemm_tf32<64, 1, 1, 3, 0, 64, 4><<<GB, 256>>>(nullptr, W1, b1, nullptr, nullptr);
    k_gatherbn<4, 0><<<AB, 256>>>();

    // GCN layer 2 (bn1-on-load + residual)
    k_gemm_tf32<64, 3, 4, 3, 0, 64, 5><<<GB, 256>>>(nullptr, W2, b2, g1, be1);
    k_gatherbn<5, 1><<<AB, 256>>>();

    k_poolheads<<<GG, 256>>>(batchw, g2, be2,
                             Wla1, bla1, Wla2, bla2, Wlo1, blo1, Wlo2, blo2, outp);
}